// round 1
// baseline (speedup 1.0000x reference)
#include <cuda_runtime.h>
#include <stdint.h>
#include <math_constants.h>

#define NBINS       256
#define N_IMG       48
#define IMG_PIX     (1024*1024)
#define TOTAL       (N_IMG*IMG_PIX)
#define TOTAL_V4    (TOTAL/4)
#define IMG_V4      (IMG_PIX/4)          // 262144 = 2^18
#define HIST_CHUNKS 32
#define VEC_PER_BLOCK (IMG_V4/HIST_CHUNKS)  // 8192

// Scratch (no allocations allowed in kernel_launch)
__device__ unsigned int g_min_m;                 // monotone-mapped float bits
__device__ unsigned int g_max_m;
__device__ unsigned int g_hist[N_IMG * NBINS];
__device__ float        g_thresh[N_IMG];

// Monotone map float -> uint (total order preserved)
__device__ __forceinline__ unsigned int fmap(float f) {
    unsigned int u = __float_as_uint(f);
    return (u & 0x80000000u) ? ~u : (u | 0x80000000u);
}
__device__ __forceinline__ float funmap(unsigned int m) {
    unsigned int u = (m & 0x80000000u) ? (m ^ 0x80000000u) : ~m;
    return __uint_as_float(u);
}

// ---------------- init: reset scratch each launch (graph replays!) ----------
__global__ void k_init() {
    int t = blockIdx.x * blockDim.x + threadIdx.x;
    if (t == 0) { g_min_m = 0xFFFFFFFFu; g_max_m = 0u; }
    for (int i = t; i < N_IMG * NBINS; i += gridDim.x * blockDim.x)
        g_hist[i] = 0u;
}

// ---------------- pass 1: global min/max ------------------------------------
__global__ void k_minmax(const float4* __restrict__ x) {
    unsigned int mn = 0xFFFFFFFFu, mx = 0u;
    for (int i = blockIdx.x * blockDim.x + threadIdx.x; i < TOTAL_V4;
         i += gridDim.x * blockDim.x) {
        float4 v = x[i];
        unsigned int a = fmap(v.x), b = fmap(v.y), c = fmap(v.z), d = fmap(v.w);
        mn = min(mn, min(min(a, b), min(c, d)));
        mx = max(mx, max(max(a, b), max(c, d)));
    }
    #pragma unroll
    for (int o = 16; o; o >>= 1) {
        mn = min(mn, __shfl_down_sync(0xffffffffu, mn, o));
        mx = max(mx, __shfl_down_sync(0xffffffffu, mx, o));
    }
    __shared__ unsigned int smn[8], smx[8];
    int w = threadIdx.x >> 5, l = threadIdx.x & 31;
    if (l == 0) { smn[w] = mn; smx[w] = mx; }
    __syncthreads();
    if (threadIdx.x == 0) {
        #pragma unroll
        for (int i = 1; i < 8; i++) { mn = min(mn, smn[i]); mx = max(mx, smx[i]); }
        atomicMin(&g_min_m, mn);
        atomicMax(&g_max_m, mx);
    }
}

// ---------------- pass 2: per-image histogram -------------------------------
// grid = N_IMG * HIST_CHUNKS blocks, 256 threads. Per-warp private smem hist
// (8 copies) so atomic conflicts are intra-warp only.
__global__ void k_hist(const float4* __restrict__ x) {
    __shared__ unsigned int sh[8 * NBINS];
    int tid = threadIdx.x;
    #pragma unroll
    for (int i = tid; i < 8 * NBINS; i += 256) sh[i] = 0u;
    __syncthreads();

    float mn = funmap(g_min_m);
    float mx = funmap(g_max_m);
    float scale = 256.0f / (mx - mn);

    int img   = blockIdx.x / HIST_CHUNKS;
    int chunk = blockIdx.x % HIST_CHUNKS;
    const float4* base = x + (size_t)img * IMG_V4 + (size_t)chunk * VEC_PER_BLOCK;

    unsigned int* myh = sh + ((tid >> 5) << 8);

    #pragma unroll 4
    for (int i = tid; i < VEC_PER_BLOCK; i += 256) {
        float4 v = base[i];
        int b0 = min(max((int)((v.x - mn) * scale), 0), 255);
        int b1 = min(max((int)((v.y - mn) * scale), 0), 255);
        int b2 = min(max((int)((v.z - mn) * scale), 0), 255);
        int b3 = min(max((int)((v.w - mn) * scale), 0), 255);
        atomicAdd(&myh[b0], 1u);
        atomicAdd(&myh[b1], 1u);
        atomicAdd(&myh[b2], 1u);
        atomicAdd(&myh[b3], 1u);
    }
    __syncthreads();

    unsigned int s = 0;
    #pragma unroll
    for (int c = 0; c < 8; c++) s += sh[(c << 8) + tid];
    if (s) atomicAdd(&g_hist[img * NBINS + tid], s);
}

// ---------------- pass 3: Otsu per image (48 tiny blocks) --------------------
__global__ void k_otsu() {
    __shared__ float h[NBINS];
    __shared__ float W[NBINS], S[NBINS];
    __shared__ float bv[NBINS];
    __shared__ int   bi[NBINS];
    int img = blockIdx.x;
    int t = threadIdx.x;

    h[t] = (float)g_hist[img * NBINS + t] * (1.0f / (float)IMG_PIX);
    __syncthreads();

    // exact sequential cumsum order (matches jnp.cumsum semantics)
    if (t == 0) {
        float cw = 0.0f, cs = 0.0f;
        for (int i = 0; i < NBINS; i++) {
            cw += h[i];            W[i] = cw;
            cs += h[i] * (float)i; S[i] = cs;
        }
    }
    __syncthreads();

    float w_bg = W[t], s_bg = S[t];
    float total = S[NBINS - 1];
    float w_fg = 1.0f - w_bg;
    float var;
    if (w_bg > 0.0f && w_fg > 0.0f) {
        float mb = s_bg / w_bg;
        float mf = (total - s_bg) / w_fg;
        float d = mb - mf;
        var = w_bg * w_fg * (d * d);
    } else {
        var = -CUDART_INF_F;
    }
    bv[t] = var; bi[t] = t;
    __syncthreads();

    // argmax, first index wins on ties (matches jnp.argmax)
    #pragma unroll
    for (int o = 128; o; o >>= 1) {
        if (t < o) {
            float vo = bv[t + o]; int io = bi[t + o];
            if (vo > bv[t] || (vo == bv[t] && io < bi[t])) { bv[t] = vo; bi[t] = io; }
        }
        __syncthreads();
    }
    if (t == 0) {
        float mn = funmap(g_min_m), mx = funmap(g_max_m);
        float span = mx - mn;
        g_thresh[img] = mn + span * ((float)(bi[0] + 1) * (1.0f / 256.0f));
    }
}

// ---------------- pass 4: thresholded write-out ------------------------------
__global__ void k_thresh(const float4* __restrict__ x, float4* __restrict__ out) {
    int i = blockIdx.x * 256 + threadIdx.x;
    if (i >= TOTAL_V4) return;
    int img = i >> 18;                 // IMG_V4 = 2^18
    float thr = __ldg(&g_thresh[img]);
    float4 v = x[i];
    float4 o;
    o.x = (v.x <= thr) ? 0.0f : v.x;
    o.y = (v.y <= thr) ? 0.0f : v.y;
    o.z = (v.z <= thr) ? 0.0f : v.z;
    o.w = (v.w <= thr) ? 0.0f : v.w;
    out[i] = o;
}

extern "C" void kernel_launch(void* const* d_in, const int* in_sizes, int n_in,
                              void* d_out, int out_size) {
    const float4* x = (const float4*)d_in[0];
    float4* out = (float4*)d_out;
    (void)in_sizes; (void)n_in; (void)out_size;

    k_init<<<48, 256>>>();
    k_minmax<<<1184, 256>>>(x);                    // 148 SMs * 8
    k_hist<<<N_IMG * HIST_CHUNKS, 256>>>(x);       // 1536 blocks
    k_otsu<<<N_IMG, 256>>>();
    k_thresh<<<TOTAL_V4 / 256, 256>>>(x, out);     // 49152 blocks
}

// round 2
// speedup vs baseline: 1.0374x; 1.0374x over previous
#include <cuda_runtime.h>
#include <stdint.h>
#include <math_constants.h>

#define NBINS       256
#define N_IMG       48
#define IMG_PIX     (1024*1024)
#define TOTAL       (N_IMG*IMG_PIX)
#define TOTAL_V4    (TOTAL/4)
#define IMG_V4      (IMG_PIX/4)              // 262144 = 2^18
#define HIST_CHUNKS 32
#define VEC_PER_BLOCK (IMG_V4/HIST_CHUNKS)   // 8192

// Persistent scratch. g_min_m/g_max_m are identity-initialized at module load
// and RE-armed at the end of every launch sequence (in k_thresh) so each graph
// replay sees the same initial state. g_phist needs no init: every slot is
// overwritten by a plain store each replay.
__device__ unsigned int g_min_m = 0xFFFFFFFFu;   // monotone-mapped float bits
__device__ unsigned int g_max_m = 0u;
__device__ unsigned int g_phist[N_IMG * HIST_CHUNKS * NBINS];  // 1.5 MB partials
__device__ float        g_thresh[N_IMG];

// Monotone map float -> uint (total order preserved)
__device__ __forceinline__ unsigned int fmap(float f) {
    unsigned int u = __float_as_uint(f);
    return (u & 0x80000000u) ? ~u : (u | 0x80000000u);
}
__device__ __forceinline__ float funmap(unsigned int m) {
    unsigned int u = (m & 0x80000000u) ? (m ^ 0x80000000u) : ~m;
    return __uint_as_float(u);
}

// ---------------- pass 1: global min/max ------------------------------------
__global__ void k_minmax(const float4* __restrict__ x) {
    unsigned int mn = 0xFFFFFFFFu, mx = 0u;
    for (int i = blockIdx.x * blockDim.x + threadIdx.x; i < TOTAL_V4;
         i += gridDim.x * blockDim.x) {
        float4 v = __ldcs(&x[i]);
        unsigned int a = fmap(v.x), b = fmap(v.y), c = fmap(v.z), d = fmap(v.w);
        mn = min(mn, min(min(a, b), min(c, d)));
        mx = max(mx, max(max(a, b), max(c, d)));
    }
    #pragma unroll
    for (int o = 16; o; o >>= 1) {
        mn = min(mn, __shfl_down_sync(0xffffffffu, mn, o));
        mx = max(mx, __shfl_down_sync(0xffffffffu, mx, o));
    }
    __shared__ unsigned int smn[8], smx[8];
    int w = threadIdx.x >> 5, l = threadIdx.x & 31;
    if (l == 0) { smn[w] = mn; smx[w] = mx; }
    __syncthreads();
    if (threadIdx.x == 0) {
        #pragma unroll
        for (int i = 1; i < 8; i++) { mn = min(mn, smn[i]); mx = max(mx, smx[i]); }
        atomicMin(&g_min_m, mn);   // only 1184 atomics total
        atomicMax(&g_max_m, mx);
    }
}

// ---------------- pass 2: per-image partial histograms (atomic-free output) --
// grid = N_IMG * HIST_CHUNKS blocks, 256 threads. Per-warp private smem hist
// (8 copies) so atomic conflicts are intra-warp only. Each block STORES its
// partial histogram; no global atomics, no zero-init pass required.
__global__ void k_hist(const float4* __restrict__ x) {
    __shared__ unsigned int sh[8 * NBINS];
    int tid = threadIdx.x;
    #pragma unroll
    for (int i = tid; i < 8 * NBINS; i += 256) sh[i] = 0u;
    __syncthreads();

    float mn = funmap(g_min_m);
    float mx = funmap(g_max_m);
    float scale = 256.0f / (mx - mn);

    int img   = blockIdx.x / HIST_CHUNKS;
    int chunk = blockIdx.x % HIST_CHUNKS;
    const float4* base = x + (size_t)img * IMG_V4 + (size_t)chunk * VEC_PER_BLOCK;

    unsigned int* myh = sh + ((tid >> 5) << 8);

    #pragma unroll 4
    for (int i = tid; i < VEC_PER_BLOCK; i += 256) {
        float4 v = __ldcs(&base[i]);
        int b0 = min(max((int)((v.x - mn) * scale), 0), 255);
        int b1 = min(max((int)((v.y - mn) * scale), 0), 255);
        int b2 = min(max((int)((v.z - mn) * scale), 0), 255);
        int b3 = min(max((int)((v.w - mn) * scale), 0), 255);
        atomicAdd(&myh[b0], 1u);
        atomicAdd(&myh[b1], 1u);
        atomicAdd(&myh[b2], 1u);
        atomicAdd(&myh[b3], 1u);
    }
    __syncthreads();

    unsigned int s = 0;
    #pragma unroll
    for (int c = 0; c < 8; c++) s += sh[(c << 8) + tid];
    g_phist[blockIdx.x * NBINS + tid] = s;   // plain store, L2-resident
}

// ---------------- pass 3: Otsu per image (48 tiny blocks) --------------------
__global__ void k_otsu() {
    __shared__ float h[NBINS];
    __shared__ float W[NBINS], S[NBINS];
    __shared__ float bv[NBINS];
    __shared__ int   bi[NBINS];
    int img = blockIdx.x;
    int t = threadIdx.x;

    // reduce 32 chunk partials for this bin (L2 hits from k_hist stores)
    unsigned int cnt = 0;
    const unsigned int* p = g_phist + img * HIST_CHUNKS * NBINS + t;
    #pragma unroll
    for (int c = 0; c < HIST_CHUNKS; c++) cnt += p[c * NBINS];
    h[t] = (float)cnt * (1.0f / (float)IMG_PIX);
    __syncthreads();

    // exact sequential cumsum order (same order as round-1 / reference):
    // batch loads 8-wide so the dep chain is only the FADDs.
    if (t == 0) {
        float cw = 0.0f, cs = 0.0f;
        #pragma unroll 4
        for (int i = 0; i < NBINS; i += 8) {
            float v0 = h[i+0], v1 = h[i+1], v2 = h[i+2], v3 = h[i+3];
            float v4 = h[i+4], v5 = h[i+5], v6 = h[i+6], v7 = h[i+7];
            cw += v0; W[i+0] = cw; cs += v0 * (float)(i+0); S[i+0] = cs;
            cw += v1; W[i+1] = cw; cs += v1 * (float)(i+1); S[i+1] = cs;
            cw += v2; W[i+2] = cw; cs += v2 * (float)(i+2); S[i+2] = cs;
            cw += v3; W[i+3] = cw; cs += v3 * (float)(i+3); S[i+3] = cs;
            cw += v4; W[i+4] = cw; cs += v4 * (float)(i+4); S[i+4] = cs;
            cw += v5; W[i+5] = cw; cs += v5 * (float)(i+5); S[i+5] = cs;
            cw += v6; W[i+6] = cw; cs += v6 * (float)(i+6); S[i+6] = cs;
            cw += v7; W[i+7] = cw; cs += v7 * (float)(i+7); S[i+7] = cs;
        }
    }
    __syncthreads();

    float w_bg = W[t], s_bg = S[t];
    float total = S[NBINS - 1];
    float w_fg = 1.0f - w_bg;
    float var;
    if (w_bg > 0.0f && w_fg > 0.0f) {
        float mb = s_bg / w_bg;
        float mf = (total - s_bg) / w_fg;
        float d = mb - mf;
        var = w_bg * w_fg * (d * d);
    } else {
        var = -CUDART_INF_F;
    }
    bv[t] = var; bi[t] = t;
    __syncthreads();

    // argmax, first index wins on ties (matches jnp.argmax)
    #pragma unroll
    for (int o = 128; o; o >>= 1) {
        if (t < o) {
            float vo = bv[t + o]; int io = bi[t + o];
            if (vo > bv[t] || (vo == bv[t] && io < bi[t])) { bv[t] = vo; bi[t] = io; }
        }
        __syncthreads();
    }
    if (t == 0) {
        float mn = funmap(g_min_m), mx = funmap(g_max_m);
        float span = mx - mn;
        g_thresh[img] = mn + span * ((float)(bi[0] + 1) * (1.0f / 256.0f));
    }
}

// ---------------- pass 4: thresholded write-out ------------------------------
__global__ void k_thresh(const float4* __restrict__ x, float4* __restrict__ out) {
    int i = blockIdx.x * 256 + threadIdx.x;
    if (i >= TOTAL_V4) return;
    int img = i >> 18;                 // IMG_V4 = 2^18
    float thr = __ldg(&g_thresh[img]);
    float4 v = __ldcs(&x[i]);
    float4 o;
    o.x = (v.x <= thr) ? 0.0f : v.x;
    o.y = (v.y <= thr) ? 0.0f : v.y;
    o.z = (v.z <= thr) ? 0.0f : v.z;
    o.w = (v.w <= thr) ? 0.0f : v.w;
    __stcs(&out[i], o);

    // Re-arm the min/max identity state for the NEXT graph replay. Nothing in
    // this launch sequence reads g_min_m/g_max_m after k_otsu, so this is safe
    // and keeps every replay deterministic.
    if (i == 0) { g_min_m = 0xFFFFFFFFu; g_max_m = 0u; }
}

extern "C" void kernel_launch(void* const* d_in, const int* in_sizes, int n_in,
                              void* d_out, int out_size) {
    const float4* x = (const float4*)d_in[0];
    float4* out = (float4*)d_out;
    (void)in_sizes; (void)n_in; (void)out_size;

    k_minmax<<<1184, 256>>>(x);                    // 148 SMs * 8
    k_hist<<<N_IMG * HIST_CHUNKS, 256>>>(x);       // 1536 blocks
    k_otsu<<<N_IMG, 256>>>();
    k_thresh<<<TOTAL_V4 / 256, 256>>>(x, out);     // 49152 blocks
}